// round 4
// baseline (speedup 1.0000x reference)
#include <cuda_runtime.h>
#include <cstdint>

// Conv(5x5, SAME) over [256,1,512,512] + FastLIF + FastLI temporal scan.
// 1024 blocks (tile 16x16) x 64 threads: near-perfect SM load balance
// (7 blocks/SM vs 6.92 ideal). Each thread: 4 consecutive cols of 1 row.
// Triple-buffered smem filled by cp.async (zfill OOB), prefetch depth 2,
// one __syncthreads per timestep. LIF/LI state in registers.

#define TT 256
#define HH 512
#define WW 512
#define HW (HH*WW)
#define TW 16        // tile width
#define THT 16       // tile height
#define NT 64        // threads per block
#define SWP 28       // smem row stride in floats (24 used; 28 -> LDS.128 conflict-free)
#define SH 20        // rows y0-2 .. y0+17
#define F4R 6        // float4 per smem row (24 cols)
#define FILLV (SH*F4R)        // 120 float4 copies per tile
#define BUFSZ (SH*SWP + 4)    // +4 floats scratch for inactive zfill slots
#define SCRATCH (SH*SWP)

#define ALPHA_LIF 0.85f
#define V_TH 2.0f
#define ALPHA_LI 0.9f

__device__ __forceinline__ void cp_async16(uint32_t dst_smem, const void* src, int srcsize) {
    asm volatile("cp.async.cg.shared.global [%0], [%1], 16, %2;\n"
                 :: "r"(dst_smem), "l"(src), "r"(srcsize));
}
__device__ __forceinline__ void cp_commit() {
    asm volatile("cp.async.commit_group;\n");
}
__device__ __forceinline__ void cp_wait1() {
    asm volatile("cp.async.wait_group 1;\n");
}

__global__ __launch_bounds__(NT, 7)
void snn_fused_kernel(const float* __restrict__ x,
                      const float* __restrict__ kern,
                      float* __restrict__ out)
{
    __shared__ float sm[3][BUFSZ];

    const int tid = threadIdx.x;
    const int x0 = blockIdx.x * TW;
    const int y0 = blockIdx.y * THT;
    const int r  = tid & 15;         // output row within tile
    const int cg = tid >> 4;         // col group: output cols x0+4cg .. +3

    // 5x5 weights in registers (uniform broadcast)
    float wgt[25];
#pragma unroll
    for (int i = 0; i < 25; i++) wgt[i] = __ldg(kern + i);

    // ---- Precompute the 2 cp.async fill slots (loop-invariant across t) ----
    // Slot j copies float4 #(tid + j*NT) of the 20-row x 6-float4 tile.
    // smem col 0 <-> global col x0-4 ; smem row 0 <-> global row y0-2.
    int soff[2], goff[2], ssz[2];
#pragma unroll
    for (int j = 0; j < 2; j++) {
        int i = tid + j * NT;
        if (i < FILLV) {
            int rr = i / F4R;
            int c4 = i - rr * F4R;
            int gy = y0 - 2 + rr;
            int gx = x0 - 4 + 4 * c4;
            bool v = (gy >= 0) && (gy < HH) && (gx >= 0) && (gx <= WW - 4);
            soff[j] = rr * SWP + 4 * c4;
            goff[j] = v ? (gy * WW + gx) : 0;
            ssz[j]  = v ? 16 : 0;
        } else {
            soff[j] = SCRATCH;   // benign dump for inactive slot
            goff[j] = 0;
            ssz[j]  = 0;
        }
    }

    // smem base addresses for the 3 buffers (rotated by pointer swap)
    uint32_t b0 = (uint32_t)__cvta_generic_to_shared(&sm[0][0]);
    uint32_t b1 = (uint32_t)__cvta_generic_to_shared(&sm[1][0]);
    uint32_t b2 = (uint32_t)__cvta_generic_to_shared(&sm[2][0]);

    // ---- Prefetch timesteps 0 and 1 ----
    {
        const float* xt = x;
#pragma unroll
        for (int j = 0; j < 2; j++) cp_async16(b0 + 4u * soff[j], xt + goff[j], ssz[j]);
        cp_commit();
        xt += HW;
#pragma unroll
        for (int j = 0; j < 2; j++) cp_async16(b1 + 4u * soff[j], xt + goff[j], ssz[j]);
        cp_commit();
    }

    // LIF / LI state for the 4 output columns
    float s1[4] = {0.f, 0.f, 0.f, 0.f};
    float s2[4] = {0.f, 0.f, 0.f, 0.f};

    const float* xp = x + 2 * (size_t)HW;                       // source for t+2
    float* op = out + (size_t)(y0 + r) * WW + x0 + 4 * cg;      // this thread's output
    const int rbase = r * SWP + 4 * cg;                         // smem read base (floats)

    for (int t = 0; t < TT; t++) {
        cp_wait1();          // tile t (in buffer b0) has landed for this thread
        __syncthreads();     // ...and for all threads; also frees b2's old readers

        // Kick off prefetch of t+2 into b2 (lands >= 2 barriers later)
        if (t + 2 < TT) {
#pragma unroll
            for (int j = 0; j < 2; j++)
                cp_async16(b2 + 4u * soff[j], xp + goff[j], ssz[j]);
        }
        cp_commit();         // unconditional: uniform wait_group accounting
        xp += HW;

        // ---- 5x5 conv for 4 consecutive output columns ----
        // Window span per row: smem cols [4cg+2, 4cg+9] -> LDS.64+LDS.128+LDS.64
        const float* rb;
        {
            // back to generic pointer for vector loads
            rb = &sm[0][0] + ((b0 - (uint32_t)__cvta_generic_to_shared(&sm[0][0])) >> 2) + rbase;
        }

        float acc0 = 0.f, acc1 = 0.f, acc2 = 0.f, acc3 = 0.f;
#pragma unroll
        for (int a = 0; a < 5; a++) {
            const float* rp = rb + a * SWP;
            float2 u  = *(const float2*)(rp + 2);
            float4 v4 = *(const float4*)(rp + 4);
            float2 w2 = *(const float2*)(rp + 8);
            float k0 = u.x,  k1 = u.y,  k2 = v4.x, k3 = v4.y;
            float k4 = v4.z, k5 = v4.w, k6 = w2.x, k7 = w2.y;
            const float* wa = wgt + a * 5;
            acc0 = fmaf(wa[0], k0, acc0);
            acc0 = fmaf(wa[1], k1, acc0);
            acc0 = fmaf(wa[2], k2, acc0);
            acc0 = fmaf(wa[3], k3, acc0);
            acc0 = fmaf(wa[4], k4, acc0);
            acc1 = fmaf(wa[0], k1, acc1);
            acc1 = fmaf(wa[1], k2, acc1);
            acc1 = fmaf(wa[2], k3, acc1);
            acc1 = fmaf(wa[3], k4, acc1);
            acc1 = fmaf(wa[4], k5, acc1);
            acc2 = fmaf(wa[0], k2, acc2);
            acc2 = fmaf(wa[1], k3, acc2);
            acc2 = fmaf(wa[2], k4, acc2);
            acc2 = fmaf(wa[3], k5, acc2);
            acc2 = fmaf(wa[4], k6, acc2);
            acc3 = fmaf(wa[0], k3, acc3);
            acc3 = fmaf(wa[1], k4, acc3);
            acc3 = fmaf(wa[2], k5, acc3);
            acc3 = fmaf(wa[3], k6, acc3);
            acc3 = fmaf(wa[4], k7, acc3);
        }

        // ---- LIF fire + soft reset, LI readout, vector store ----
        float4 o;
        {
            float v0 = fmaf(ALPHA_LIF, s1[0], acc0);
            float v1 = fmaf(ALPHA_LIF, s1[1], acc1);
            float v2 = fmaf(ALPHA_LIF, s1[2], acc2);
            float v3 = fmaf(ALPHA_LIF, s1[3], acc3);
            float p0 = (v0 >= V_TH) ? 1.0f : 0.0f;
            float p1 = (v1 >= V_TH) ? 1.0f : 0.0f;
            float p2 = (v2 >= V_TH) ? 1.0f : 0.0f;
            float p3 = (v3 >= V_TH) ? 1.0f : 0.0f;
            s1[0] = fmaf(p0, -V_TH, v0);
            s1[1] = fmaf(p1, -V_TH, v1);
            s1[2] = fmaf(p2, -V_TH, v2);
            s1[3] = fmaf(p3, -V_TH, v3);
            s2[0] = fmaf(ALPHA_LI, s2[0], p0);
            s2[1] = fmaf(ALPHA_LI, s2[1], p1);
            s2[2] = fmaf(ALPHA_LI, s2[2], p2);
            s2[3] = fmaf(ALPHA_LI, s2[3], p3);
            o.x = s2[0]; o.y = s2[1]; o.z = s2[2]; o.w = s2[3];
        }
        *(float4*)op = o;
        op += HW;

        // Rotate buffers: b0 <- b1 <- b2 <- b0
        uint32_t tb = b0; b0 = b1; b1 = b2; b2 = tb;
    }
}

extern "C" void kernel_launch(void* const* d_in, const int* in_sizes, int n_in,
                              void* d_out, int out_size)
{
    const float* x = (const float*)d_in[0];
    const float* k = (const float*)d_in[1];
    if (in_sizes[0] == 25) {  // defensive: swap if metadata order differs
        const float* tmp = x; x = k; k = tmp;
    }
    float* out = (float*)d_out;

    dim3 grid(WW / TW, HH / THT);   // 32 x 32 = 1024 blocks
    snn_fused_kernel<<<grid, NT>>>(x, k, out);
}

// round 5
// speedup vs baseline: 1.4729x; 1.4729x over previous
#include <cuda_runtime.h>
#include <cstdint>

// Conv(5x5, SAME) over [256,1,512,512] + FastLIF + FastLI temporal scan.
// Tile 64x16 per block (grid 256), 128 threads; each thread computes
// 2 rows x 4 cols (vertical register reuse: 6 input rows feed 2 output
// rows -> 40% less shared-memory read traffic). Triple-buffered smem via
// cp.async (zfill OOB), prefetch depth 2, one __syncthreads per timestep.

#define TT 256
#define HH 512
#define WW 512
#define HW (HH*WW)
#define TW 64        // tile width
#define THT 16       // tile height
#define NT 128       // threads per block (4 warps)
#define SWP 72       // smem row stride in floats (cols x0-4 .. x0+67)
#define SH 20        // rows y0-2 .. y0+17
#define F4R 18       // float4 per smem row
#define FILLV (SH*F4R)        // 360 float4 copies per tile
#define PF 3                  // ceil(360/128) fill slots per thread
#define BUFSZ (SH*SWP + 4)    // +4 floats scratch for inactive zfill slots
#define SCRATCH (SH*SWP)

#define ALPHA_LIF 0.85f
#define V_TH 2.0f
#define ALPHA_LI 0.9f

__device__ __forceinline__ void cp_async16(uint32_t dst_smem, const void* src, int srcsize) {
    asm volatile("cp.async.cg.shared.global [%0], [%1], 16, %2;\n"
                 :: "r"(dst_smem), "l"(src), "r"(srcsize));
}
__device__ __forceinline__ void cp_commit() {
    asm volatile("cp.async.commit_group;\n");
}
__device__ __forceinline__ void cp_wait1() {
    asm volatile("cp.async.wait_group 1;\n");
}

__global__ __launch_bounds__(NT, 2)
void snn_fused_kernel(const float* __restrict__ x,
                      const float* __restrict__ kern,
                      float* __restrict__ out)
{
    __shared__ float sm[3][BUFSZ];

    const int tid = threadIdx.x;
    const int x0 = blockIdx.x * TW;
    const int y0 = blockIdx.y * THT;
    const int tc = tid & 15;          // col group: output cols x0+4tc .. +3
    const int rg = tid >> 4;          // row-pair group: output rows y0+2rg, y0+2rg+1

    // 5x5 weights in registers (uniform broadcast)
    float wgt[25];
#pragma unroll
    for (int i = 0; i < 25; i++) wgt[i] = __ldg(kern + i);

    // ---- Precompute the PF cp.async fill slots (loop-invariant across t) ----
    // Slot j copies float4 #(tid + j*NT) of the 20-row x 18-float4 tile.
    // smem col 0 <-> global col x0-4 ; smem row 0 <-> global row y0-2.
    int soff[PF], goff[PF], ssz[PF];
#pragma unroll
    for (int j = 0; j < PF; j++) {
        int i = tid + j * NT;
        if (i < FILLV) {
            int rr = i / F4R;
            int c4 = i - rr * F4R;
            int gy = y0 - 2 + rr;
            int gx = x0 - 4 + 4 * c4;
            bool v = (gy >= 0) && (gy < HH) && (gx >= 0) && (gx <= WW - 4);
            soff[j] = rr * SWP + 4 * c4;
            goff[j] = v ? (gy * WW + gx) : 0;
            ssz[j]  = v ? 16 : 0;
        } else {
            soff[j] = SCRATCH;   // benign dump for inactive slot
            goff[j] = 0;
            ssz[j]  = 0;
        }
    }

    // u32 smem bases for cp.async (rotated), generic index for LDS reads
    uint32_t c0 = (uint32_t)__cvta_generic_to_shared(&sm[0][0]);
    uint32_t c1 = (uint32_t)__cvta_generic_to_shared(&sm[1][0]);
    uint32_t c2 = (uint32_t)__cvta_generic_to_shared(&sm[2][0]);
    int bi = 0;   // which sm[] buffer is the front (read) buffer

    // ---- Prefetch timesteps 0 and 1 ----
    {
        const float* xt = x;
#pragma unroll
        for (int j = 0; j < PF; j++) cp_async16(c0 + 4u * soff[j], xt + goff[j], ssz[j]);
        cp_commit();
        xt += HW;
#pragma unroll
        for (int j = 0; j < PF; j++) cp_async16(c1 + 4u * soff[j], xt + goff[j], ssz[j]);
        cp_commit();
    }

    // LIF / LI state: 2 rows x 4 cols
    float s1[8], s2[8];
#pragma unroll
    for (int i = 0; i < 8; i++) { s1[i] = 0.f; s2[i] = 0.f; }

    const float* xp = x + 2 * (size_t)HW;                        // source for t+2
    float* op = out + (size_t)(y0 + 2 * rg) * WW + x0 + 4 * tc;  // row 0 of pair
    const int rbase = (2 * rg) * SWP + 4 * tc;                   // smem read base

    for (int t = 0; t < TT; t++) {
        cp_wait1();          // tile t (front buffer) has landed for this thread
        __syncthreads();     // ...for all threads; also frees the third buffer

        // Prefetch t+2 into the freed buffer (c2)
        if (t + 2 < TT) {
#pragma unroll
            for (int j = 0; j < PF; j++)
                cp_async16(c2 + 4u * soff[j], xp + goff[j], ssz[j]);
        }
        cp_commit();         // unconditional: uniform wait_group accounting
        xp += HW;

        // ---- 5x5 conv: 2 output rows x 4 cols from 6 streamed input rows ----
        const float* rb = &sm[bi][0] + rbase;

        float a0 = 0.f, a1 = 0.f, a2 = 0.f, a3 = 0.f;   // output row 2rg
        float d0 = 0.f, d1 = 0.f, d2 = 0.f, d3 = 0.f;   // output row 2rg+1
#pragma unroll
        for (int j = 0; j < 6; j++) {
            const float* rp = rb + j * SWP;
            float2 u  = *(const float2*)(rp + 2);
            float4 v4 = *(const float4*)(rp + 4);
            float2 w2 = *(const float2*)(rp + 8);
            float k0 = u.x,  k1 = u.y,  k2 = v4.x, k3 = v4.y;
            float k4 = v4.z, k5 = v4.w, k6 = w2.x, k7 = w2.y;
            if (j < 5) {                     // contributes to row 2rg with tap a=j
                const float* wa = wgt + j * 5;
                a0 = fmaf(wa[0], k0, a0); a0 = fmaf(wa[1], k1, a0);
                a0 = fmaf(wa[2], k2, a0); a0 = fmaf(wa[3], k3, a0);
                a0 = fmaf(wa[4], k4, a0);
                a1 = fmaf(wa[0], k1, a1); a1 = fmaf(wa[1], k2, a1);
                a1 = fmaf(wa[2], k3, a1); a1 = fmaf(wa[3], k4, a1);
                a1 = fmaf(wa[4], k5, a1);
                a2 = fmaf(wa[0], k2, a2); a2 = fmaf(wa[1], k3, a2);
                a2 = fmaf(wa[2], k4, a2); a2 = fmaf(wa[3], k5, a2);
                a2 = fmaf(wa[4], k6, a2);
                a3 = fmaf(wa[0], k3, a3); a3 = fmaf(wa[1], k4, a3);
                a3 = fmaf(wa[2], k5, a3); a3 = fmaf(wa[3], k6, a3);
                a3 = fmaf(wa[4], k7, a3);
            }
            if (j > 0) {                     // contributes to row 2rg+1 with tap a=j-1
                const float* wb = wgt + (j - 1) * 5;
                d0 = fmaf(wb[0], k0, d0); d0 = fmaf(wb[1], k1, d0);
                d0 = fmaf(wb[2], k2, d0); d0 = fmaf(wb[3], k3, d0);
                d0 = fmaf(wb[4], k4, d0);
                d1 = fmaf(wb[0], k1, d1); d1 = fmaf(wb[1], k2, d1);
                d1 = fmaf(wb[2], k3, d1); d1 = fmaf(wb[3], k4, d1);
                d1 = fmaf(wb[4], k5, d1);
                d2 = fmaf(wb[0], k2, d2); d2 = fmaf(wb[1], k3, d2);
                d2 = fmaf(wb[2], k4, d2); d2 = fmaf(wb[3], k5, d2);
                d2 = fmaf(wb[4], k6, d2);
                d3 = fmaf(wb[0], k3, d3); d3 = fmaf(wb[1], k4, d3);
                d3 = fmaf(wb[2], k5, d3); d3 = fmaf(wb[3], k6, d3);
                d3 = fmaf(wb[4], k7, d3);
            }
        }

        // ---- LIF fire + soft reset, LI readout, two vector stores ----
        float acc[8] = {a0, a1, a2, a3, d0, d1, d2, d3};
        float o[8];
#pragma unroll
        for (int i = 0; i < 8; i++) {
            float v = fmaf(ALPHA_LIF, s1[i], acc[i]);
            float spk = (v >= V_TH) ? 1.0f : 0.0f;
            s1[i] = fmaf(spk, -V_TH, v);
            s2[i] = fmaf(ALPHA_LI, s2[i], spk);
            o[i] = s2[i];
        }
        float4 o0 = {o[0], o[1], o[2], o[3]};
        float4 o1 = {o[4], o[5], o[6], o[7]};
        *(float4*)op = o0;
        *(float4*)(op + WW) = o1;
        op += HW;

        // Rotate buffers: front <- c1 <- c2 <- old front
        uint32_t tb = c0; c0 = c1; c1 = c2; c2 = tb;
        bi = (bi == 2) ? 0 : bi + 1;
    }
}

extern "C" void kernel_launch(void* const* d_in, const int* in_sizes, int n_in,
                              void* d_out, int out_size)
{
    const float* x = (const float*)d_in[0];
    const float* k = (const float*)d_in[1];
    if (in_sizes[0] == 25) {  // defensive: swap if metadata order differs
        const float* tmp = x; x = k; k = tmp;
    }
    float* out = (float*)d_out;

    dim3 grid(WW / TW, HH / THT);   // 8 x 32 = 256 blocks
    snn_fused_kernel<<<grid, NT>>>(x, k, out);
}